// round 15
// baseline (speedup 1.0000x reference)
#include <cuda_runtime.h>
#include <cfloat>

// Problem constants (from reference)
#define PB 7      // pooled bins per dim
#define HH 50
#define WW 50
#define CC 512
#define BB 2
#define RR 64
#define C4 (CC / 4)     // 128 float4 per pixel
#define NBINS (BB * RR * PB * PB)   // 6272
#define NCTA  2368                  // 148 SMs x 16 CTAs: full-residency wave
#define N3    1536                  // CTAs that take 3 bins (rest take 2)
                                    // 1536*3 + 832*2 = 6272

// Refinement of the best-measured config (grid 2368, R13 ncu 10.18us):
// each CTA owns a CONTIGUOUS run of 2-3 bins. A contiguous run spans at
// most 2 rois (49 bins/roi), so both rois are prefetched up front and the
// per-bin path has zero loads of roi data and zero div/mod — bin->(py,px)
// is decoded once and then incremented. Stores become 4-6KB contiguous.
//
// Integer bin bounds ys = py*h/7 == reference fp32 trunc(py*(h/7.0f)) for
// h in [7,25]: exact when 7|h, else py*h/7 is >=1/7 from any integer, far
// beyond fp32 rounding error. (Validated rel_err=0.0 in R10-R14.)
//
// Facts proved from input ranges: extent in [7,26) => sy,sx in [1,4];
// window always fully in-bounds (max index y0+h-1 <= 48 < 50).

__device__ __forceinline__ void vmax(float4& m, float4 v) {
    m.x = fmaxf(m.x, v.x);
    m.y = fmaxf(m.y, v.y);
    m.z = fmaxf(m.z, v.z);
    m.w = fmaxf(m.w, v.w);
}

template<int SY, int SX>
__device__ __forceinline__ float4 binmax(const float4* __restrict__ p) {
    float4 v[SY * SX];
    #pragma unroll
    for (int dy = 0; dy < SY; ++dy)
        #pragma unroll
        for (int dx = 0; dx < SX; ++dx)
            v[dy * SX + dx] = __ldg(p + (dy * WW + dx) * C4);

    float4 m = v[0];
    #pragma unroll
    for (int k = 1; k < SY * SX; ++k)
        vmax(m, v[k]);
    return m;
}

__global__ __launch_bounds__(C4) void roipool_kernel(
    const float4* __restrict__ fm,    // (B,H,W,C) as float4
    const int*    __restrict__ rois,  // (B,R,4) int32: y0,x0,h,w
    float4*       __restrict__ out)   // (B,R,P,P,C) as float4
{
    int bid = blockIdx.x;             // 0..2367
    int start, cnt;
    if (bid < N3) { start = bid * 3;              cnt = 3; }
    else          { start = N3 * 3 + (bid - N3) * 2; cnt = 2; }

    int c4 = threadIdx.x;             // 0..127

    // Decode the first bin once; afterwards only increments.
    int rid  = start / (PB * PB);
    int obin = start - rid * (PB * PB);
    int py   = obin / PB;
    int px   = obin - py * PB;

    // Prefetch this roi and (possibly) the next one — a 2-3 bin contiguous
    // run touches at most 2 rois.
    int4 roi  = __ldg((const int4*)(rois + rid * 4));
    int  rid1 = min(rid + 1, BB * RR - 1);
    int4 roi1 = __ldg((const int4*)(rois + rid1 * 4));

    int b = rid >> 6;                 // batch of the current roi

    #pragma unroll
    for (int k = 0; k < 3; ++k) {
        if (k >= cnt) break;

        int y0 = roi.x, x0 = roi.y, h = roi.z, w = roi.w;

        // Integer bin bounds (== reference fp32 result, see header).
        int ys = (py * h) / PB;
        int ye = (py == PB - 1) ? h : ((py + 1) * h) / PB;
        int sy = max(ye - ys, 1);
        int xs = (px * w) / PB;
        int xe = (px == PB - 1) ? w : ((px + 1) * w) / PB;
        int sx = max(xe - xs, 1);

        const float4* p = fm
            + ((size_t)((b * HH + (y0 + ys)) * WW + (x0 + xs))) * C4
            + c4;

        float4 m;
        int code = (sy - 1) * 4 + (sx - 1);   // uniform across CTA
        switch (code) {
            case  0: m = binmax<1,1>(p); break;
            case  1: m = binmax<1,2>(p); break;
            case  2: m = binmax<1,3>(p); break;
            case  3: m = binmax<1,4>(p); break;
            case  4: m = binmax<2,1>(p); break;
            case  5: m = binmax<2,2>(p); break;
            case  6: m = binmax<2,3>(p); break;
            case  7: m = binmax<2,4>(p); break;
            case  8: m = binmax<3,1>(p); break;
            case  9: m = binmax<3,2>(p); break;
            case 10: m = binmax<3,3>(p); break;
            case 11: m = binmax<3,4>(p); break;
            case 12: m = binmax<4,1>(p); break;
            case 13: m = binmax<4,2>(p); break;
            case 14: m = binmax<4,3>(p); break;
            default: m = binmax<4,4>(p); break;
        }

        out[(size_t)(start + k) * C4 + c4] = m;

        // Advance to the next contiguous bin (no div/mod).
        if (++px == PB) {
            px = 0;
            if (++py == PB) {
                py = 0;
                roi = roi1;           // crossed into the next roi
                b = rid1 >> 6;
            }
        }
    }
}

extern "C" void kernel_launch(void* const* d_in, const int* in_sizes, int n_in,
                              void* d_out, int out_size) {
    const float4* fm   = (const float4*)d_in[0];  // x_maps float32 (2,50,50,512)
    const int*    rois = (const int*)d_in[1];     // x_rois int32 (2,64,4)
    float4*       out  = (float4*)d_out;          // (2,64,7,7,512) float32

    roipool_kernel<<<NCTA, C4>>>(fm, rois, out);
}

// round 16
// speedup vs baseline: 1.0492x; 1.0492x over previous
#include <cuda_runtime.h>
#include <cfloat>

// Problem constants (from reference)
#define PB 7      // pooled bins per dim
#define HH 50
#define WW 50
#define CC 512
#define BB 2
#define RR 64
#define C4 (CC / 4)     // 128 float4 per pixel
#define NBINS (BB * RR * PB * PB)   // 6272
#define NCTA  (NBINS / 4)           // 1568: 4 bins per CTA

// FINAL (best measured: 10.21us, R12). Structure:
//  * CTA i handles bins {i, i+1568, i+3136, i+4704}. 1568 = 32*49, so all 4
//    bins share one (py,px) — decoded once — and rid advances by 32: zero
//    div/mod on the per-bin path.
//  * roi for iteration k+1 is loaded before iteration k's gather, so its L2
//    latency is covered by the gather instead of sitting on the chain.
//  * integer bin bounds ys = py*h/7 (== reference fp32 trunc(py*(h/7.0f))
//    for h in [7,25]: exact when 7|h, else py*h/7 is >=1/7 from any integer,
//    far beyond fp32 rounding error; validated rel_err=0.0 across rounds).
//  * (sy,sx) is CTA-uniform -> 16-case exact-load dispatch: each case is a
//    compile-time batch of sy*sx independent LDG.128 (max MLP, no predicate
//    waste) followed by an fmax tree.
//
// Facts proved from input ranges: extent in [7,26) => sy,sx in [1,4];
// window always fully in-bounds (max index y0+h-1 <= 48 < 50).

__device__ __forceinline__ void vmax(float4& m, float4 v) {
    m.x = fmaxf(m.x, v.x);
    m.y = fmaxf(m.y, v.y);
    m.z = fmaxf(m.z, v.z);
    m.w = fmaxf(m.w, v.w);
}

template<int SY, int SX>
__device__ __forceinline__ float4 binmax(const float4* __restrict__ p) {
    float4 v[SY * SX];
    #pragma unroll
    for (int dy = 0; dy < SY; ++dy)
        #pragma unroll
        for (int dx = 0; dx < SX; ++dx)
            v[dy * SX + dx] = __ldg(p + (dy * WW + dx) * C4);

    float4 m = v[0];
    #pragma unroll
    for (int k = 1; k < SY * SX; ++k)
        vmax(m, v[k]);
    return m;
}

__global__ __launch_bounds__(C4) void roipool_kernel(
    const float4* __restrict__ fm,    // (B,H,W,C) as float4
    const int*    __restrict__ rois,  // (B,R,4) int32: y0,x0,h,w
    float4*       __restrict__ out)   // (B,R,P,P,C) as float4
{
    int binbase = blockIdx.x;         // 0..1567
    int px   = binbase % PB;
    int py   = (binbase / PB) % PB;
    int rid0 = binbase / (PB * PB);   // 0..31; iterations use rid0 + 32k

    int c4 = threadIdx.x;             // 0..127
    bool lasty = (py == PB - 1);
    bool lastx = (px == PB - 1);
    int obin = py * PB + px;

    // First roi load issues immediately.
    int4 roi = __ldg((const int4*)(rois + rid0 * 4));

    #pragma unroll
    for (int k = 0; k < 4; ++k) {
        int rid = rid0 + 32 * k;

        // Issue next roi load BEFORE this bin's gather so its latency is
        // covered by the gather's loads.
        int4 roi_n;
        if (k < 3)
            roi_n = __ldg((const int4*)(rois + (rid + 32) * 4));

        int y0 = roi.x, x0 = roi.y, h = roi.z, w = roi.w;

        // Integer bin bounds (== reference fp32 result, see header).
        int ys = (py * h) / PB;
        int ye = lasty ? h : ((py + 1) * h) / PB;
        int sy = max(ye - ys, 1);
        int xs = (px * w) / PB;
        int xe = lastx ? w : ((px + 1) * w) / PB;
        int sx = max(xe - xs, 1);

        // b = rid >> 6; fm image stride = HH*WW pixels.
        const float4* p = fm
            + ((size_t)(((rid >> 6) * HH + (y0 + ys)) * WW + (x0 + xs))) * C4
            + c4;

        float4 m;
        int code = (sy - 1) * 4 + (sx - 1);   // uniform across CTA
        switch (code) {
            case  0: m = binmax<1,1>(p); break;
            case  1: m = binmax<1,2>(p); break;
            case  2: m = binmax<1,3>(p); break;
            case  3: m = binmax<1,4>(p); break;
            case  4: m = binmax<2,1>(p); break;
            case  5: m = binmax<2,2>(p); break;
            case  6: m = binmax<2,3>(p); break;
            case  7: m = binmax<2,4>(p); break;
            case  8: m = binmax<3,1>(p); break;
            case  9: m = binmax<3,2>(p); break;
            case 10: m = binmax<3,3>(p); break;
            case 11: m = binmax<3,4>(p); break;
            case 12: m = binmax<4,1>(p); break;
            case 13: m = binmax<4,2>(p); break;
            case 14: m = binmax<4,3>(p); break;
            default: m = binmax<4,4>(p); break;
        }

        out[(size_t)(rid * (PB * PB) + obin) * C4 + c4] = m;

        roi = roi_n;
    }
}

extern "C" void kernel_launch(void* const* d_in, const int* in_sizes, int n_in,
                              void* d_out, int out_size) {
    const float4* fm   = (const float4*)d_in[0];  // x_maps float32 (2,50,50,512)
    const int*    rois = (const int*)d_in[1];     // x_rois int32 (2,64,4)
    float4*       out  = (float4*)d_out;          // (2,64,7,7,512) float32

    roipool_kernel<<<NCTA, C4>>>(fm, rois, out);
}